// round 11
// baseline (speedup 1.0000x reference)
#include <cuda_runtime.h>

// LSTMBrain: 2-layer LSTM (hidden=3) over [B=4096, T=2048], dense head 3->1.
// Round 11: latency-coverage design. 16 lanes per element -> 2048 warps
// (~3.46 per SMSP) so the ~230-cycle per-step dependency chain is hidden by
// warp interleaving (R2-R10 all ran 1-2 warps/SMSP and were chain-bound).
//   group = 16 lanes (2 groups/warp). pair p = lane16>>1:
//     p 0-2: layer-1 unit p | p 3: dup of unit 2 | p 4-6: layer-2 unit p-4 |
//     p 7: dup. sub-lane 0: gates (i,f); sub-lane 1: gates (g,o).
//   Each lane: ONE f32x2 z (7 ffma2), 2 gate ex2. Exchange A swaps the pair's
//   gate exponentials (STS.64+syncwarp+LDS.128); all lanes then compute the
//   cell redundantly (convergent stream, 3 more MUFU). Exchange B broadcasts
//   outv (R9 scheme: STS.64 + syncwarp + 3x LDS.128 of duplicated values).
//   5 MUFU / lane / step. Single-buffered smem is race-free (2 syncs/step).

typedef unsigned long long u64;

#define FULLM 0xFFFFFFFFu
#define LOG2E 1.4426950408889634f

__device__ __forceinline__ float fast_rcp(float x) {
    float r; asm("rcp.approx.f32 %0, %1;" : "=f"(r) : "f"(x)); return r;
}
__device__ __forceinline__ float fast_ex2(float x) {
    float r; asm("ex2.approx.f32 %0, %1;" : "=f"(r) : "f"(x)); return r;
}
__device__ __forceinline__ u64 ffma2(u64 a, u64 b, u64 c) {
    u64 d; asm("fma.rn.f32x2 %0, %1, %2, %3;" : "=l"(d) : "l"(a), "l"(b), "l"(c));
    return d;
}
__device__ __forceinline__ u64 fmul2(u64 a, u64 b) {
    u64 d; asm("mul.rn.f32x2 %0, %1, %2;" : "=l"(d) : "l"(a), "l"(b)); return d;
}
__device__ __forceinline__ u64 fadd2(u64 a, u64 b) {
    u64 d; asm("add.rn.f32x2 %0, %1, %2;" : "=l"(d) : "l"(a), "l"(b)); return d;
}
__device__ __forceinline__ u64 pack2(float lo, float hi) {
    u64 d; asm("mov.b64 %0, {%1, %2};" : "=l"(d) : "f"(lo), "f"(hi)); return d;
}
__device__ __forceinline__ void unpack2(u64 v, float& lo, float& hi) {
    asm("mov.b64 {%0, %1}, %2;" : "=f"(lo), "=f"(hi) : "l"(v));
}

__global__ void __launch_bounds__(32, 1) lstm2_r11_kernel(
    const float* __restrict__ state,
    const float* __restrict__ W1, const float* __restrict__ U1, const float* __restrict__ b1,
    const float* __restrict__ W2, const float* __restrict__ U2, const float* __restrict__ b2,
    const float* __restrict__ Wd, const float* __restrict__ bd,
    float* __restrict__ out, int B, int T)
{
    __shared__ __align__(16) u64 rgA[2][16];   // gate-exponential exchange
    __shared__ __align__(16) u64 rgB[2][16];   // outv broadcast (slots 0-5 live)

    const int lane = threadIdx.x & 31;
    const int gidx = lane >> 4;                // group within warp (0/1)
    const int l16  = lane & 15;
    const int p    = l16 >> 1;                 // pair 0..7
    const int sub  = l16 & 1;                  // 0: (i,f) gates, 1: (g,o)
    const bool isL2 = (p >= 4);
    const int u = (p < 3) ? p : (p == 3 ? 2 : (p < 7 ? p - 4 : 2));

    // exchange-B write slot (unique per lane within group):
    // sub0: p0,1,2 -> 0,1,2 (s1 units); p4,5,6 -> 3,4,5 (h2 units); p3->6,p7->7
    // sub1: 8+p (spare)
    const int ws = sub ? (8 + p)
                       : ((p < 3) ? p : (p >= 4 && p < 7) ? (p - 1)
                                      : (p == 3 ? 6 : 7));

    int e = blockIdx.x * 2 + gidx;             // element of this group
    const bool act = (e < B);
    if (!act) e = B - 1;

    // ---- per-lane coefficients for its 2 gates, pre-scaled into ex2 domain
    // gates: sub0 -> (0:i, 1:f), sub1 -> (2:g tanh, 3:o); column = gate*3+u
    const int g_lo = sub ? 2 : 0, g_hi = sub ? 3 : 1;
    const float s_lo = sub ? (-2.0f * LOG2E) : (-LOG2E);
    const float s_hi = -LOG2E;
    const int c_lo = g_lo * 3 + u, c_hi = g_hi * 3 + u;

    u64 A, BI, Bk[3], Ck[3];
    if (isL2) {
        A  = 0;
        BI = pack2(__ldg(b2 + c_lo) * s_lo, __ldg(b2 + c_hi) * s_hi);
#pragma unroll
        for (int k = 0; k < 3; ++k) {
            Bk[k] = pack2(__ldg(W2 + k * 12 + c_lo) * s_lo,
                          __ldg(W2 + k * 12 + c_hi) * s_hi);   // * s1 bcast
            Ck[k] = pack2(__ldg(U2 + k * 12 + c_lo) * s_lo,
                          __ldg(U2 + k * 12 + c_hi) * s_hi);   // * h2 bcast
        }
    } else {
        A  = pack2(__ldg(W1 + c_lo) * s_lo, __ldg(W1 + c_hi) * s_hi);
        BI = pack2(__ldg(b1 + c_lo) * s_lo, __ldg(b1 + c_hi) * s_hi);
#pragma unroll
        for (int k = 0; k < 3; ++k) {
            Bk[k] = pack2(__ldg(U1 + k * 12 + c_lo) * s_lo,
                          __ldg(U1 + k * 12 + c_hi) * s_hi);   // * s1 bcast
            Ck[k] = 0;
        }
    }

    const float* xrow = state + (size_t)e * (size_t)T;

    float cc   = 0.f;                     // own-unit scaled cell (-2L*c), dup per pair
    float outv = 0.f;                     // own-unit hidden output, dup per pair
    u64 S0 = 0, S1 = 0, S2 = 0;           // duplicated s1(t-1) broadcasts
    u64 H0 = 0, H1 = 0, H2 = 0;           // duplicated h2(t-1 for L2) broadcasts

    // STEP: z (7 ffma2) -> 2 gate ex2 -> exchange A -> redundant cell -> outv
#define STEP(xv)                                                            \
    do {                                                                    \
        const u64 xp  = pack2((xv), (xv));                                  \
        const u64 pre = ffma2(A, xp, BI);                                   \
        u64 uu = ffma2(Bk[0], S0, pre);                                     \
        uu = ffma2(Bk[1], S1, uu);                                          \
        uu = ffma2(Bk[2], S2, uu);                                          \
        u64 vv = fmul2(Ck[2], H2);                                          \
        vv = ffma2(Ck[0], H0, vv);                                          \
        vv = ffma2(Ck[1], H1, vv);                                          \
        const u64 z = fadd2(uu, vv);                                        \
        float zl, zh;                                                       \
        unpack2(z, zl, zh);                                                 \
        const float el = fast_ex2(zl);                                      \
        const float eh = fast_ex2(zh);                                      \
        rgA[gidx][l16] = pack2(el, eh);                                     \
        __syncwarp(FULLM);                                                  \
        const ulonglong2 ee =                                               \
            *reinterpret_cast<const ulonglong2*>(&rgA[gidx][p << 1]);       \
        float ei, ef, eg, eo;                                               \
        unpack2(ee.x, ei, ef); unpack2(ee.y, eg, eo);                       \
        const float di = 1.0f + ei, df = 1.0f + ef;                         \
        const float dg = 1.0f + eg, dq = 1.0f + eo;                         \
        const float m1 = di * dg;                                           \
        const float m2 = m1 * df;                                           \
        const float Rm = fast_rcp(m2);                                      \
        const float sf  = Rm * m1;    /* 1/df  (forget gate) */             \
        const float r02 = Rm * df;    /* 1/(di*dg) */                       \
        const float pp  = fmaf(2.0f * LOG2E, eg, -2.0f * LOG2E);            \
        cc = fmaf(sf, cc, pp * r02);  /* cc = -2L * c */                    \
        const float ec = fast_ex2(cc);                                      \
        const float dc = 1.0f + ec;                                         \
        const float Rq = fast_rcp(dc * dq);                                 \
        outv = (1.0f - ec) * Rq;      /* tanh(c) * sigmoid(o) */            \
    } while (0)

    // exchange B: broadcast outv (duplicated u64), read S/H vectors
#define XCHGB()                                                             \
    do {                                                                    \
        rgB[gidx][ws] = pack2(outv, outv);                                  \
        __syncwarp(FULLM);                                                  \
        const ulonglong2 v0 =                                               \
            *reinterpret_cast<const ulonglong2*>(&rgB[gidx][0]);            \
        const ulonglong2 v1 =                                               \
            *reinterpret_cast<const ulonglong2*>(&rgB[gidx][2]);            \
        const ulonglong2 v2 =                                               \
            *reinterpret_cast<const ulonglong2*>(&rgB[gidx][4]);            \
        S0 = v0.x; S1 = v0.y; S2 = v1.x;                                    \
        H0 = v1.y; H1 = v2.x; H2 = v2.y;                                    \
    } while (0)

#define BODY(xv) do { STEP(xv); XCHGB(); } while (0)

    // ---- prologue: t = 0 (L2 lanes computed garbage: no h2(-1); reset
    // before the first broadcast), then t = 1..3 from the first chunk.
    float4 a4 = __ldg(reinterpret_cast<const float4*>(xrow));
    float4 nA = a4;
    if (T >= 8) nA = __ldg(reinterpret_cast<const float4*>(xrow + 4));

    STEP(a4.x);
    if (isL2) { cc = 0.f; outv = 0.f; }
    XCHGB();
    BODY(a4.y);
    BODY(a4.z);
    BODY(a4.w);

    int t = 4;
    for (; t + 7 < T; t += 4) {
        a4 = nA;
        nA = __ldg(reinterpret_cast<const float4*>(xrow + t + 4));
        BODY(a4.x);
        BODY(a4.y);
        BODY(a4.z);
        BODY(a4.w);
    }
    if (t + 3 < T) {                      // last full chunk (already prefetched)
        a4 = nA;
        BODY(a4.x);
        BODY(a4.y);
        BODY(a4.z);
        BODY(a4.w);
        t += 4;
    }
    for (; t < T; ++t) {                  // scalar tail (not taken for T=2048)
        BODY(__ldg(xrow + t));
    }

    // ---- epilogue: one more step so L2 pairs produce h2(T-1). x unused by
    // L2 (A = 0); L1 output never consumed.
    STEP(0.0f);
    rgB[gidx][ws] = pack2(outv, outv);
    __syncwarp(FULLM);

    if (l16 == 0 && act) {
        float f0, f1, f2, junk;
        unpack2(rgB[gidx][3], f0, junk);   // h2 unit 0
        unpack2(rgB[gidx][4], f1, junk);   // h2 unit 1
        unpack2(rgB[gidx][5], f2, junk);   // h2 unit 2
        float r = __ldg(bd);
        r = fmaf(f0, __ldg(Wd + 0), r);
        r = fmaf(f1, __ldg(Wd + 1), r);
        r = fmaf(f2, __ldg(Wd + 2), r);
        out[e] = r;
    }

#undef STEP
#undef XCHGB
#undef BODY
}

extern "C" void kernel_launch(void* const* d_in, const int* in_sizes, int n_in,
                              void* d_out, int out_size)
{
    const float* state = (const float*)d_in[0];
    const float* W1 = (const float*)d_in[1];
    const float* U1 = (const float*)d_in[2];
    const float* b1 = (const float*)d_in[3];
    const float* W2 = (const float*)d_in[4];
    const float* U2 = (const float*)d_in[5];
    const float* b2 = (const float*)d_in[6];
    const float* Wd = (const float*)d_in[7];
    const float* bd = (const float*)d_in[8];
    float* out = (float*)d_out;

    const int B = out_size;            // output is [1, B]
    const int T = in_sizes[0] / B;     // state is [B, T]

    const int elems_per_block = 2;     // 2 groups x 16 lanes = 32 threads
    const int blocks = (B + elems_per_block - 1) / elems_per_block;  // 2048
    lstm2_r11_kernel<<<blocks, 32>>>(state, W1, U1, b1, W2, U2, b2,
                                     Wd, bd, out, B, T);
}

// round 12
// speedup vs baseline: 1.0105x; 1.0105x over previous
#include <cuda_runtime.h>

// LSTMBrain: 2-layer LSTM (hidden=3) over [B=4096, T=2048], dense head 3->1.
// Round 12: LAYER-PER-LANE. Even lane = entire layer 1 of element e, odd lane
// = entire layer 2. Both recurrence cycles are IN-REGISTER (no exchange in
// the chain!). The only cross-lane traffic is the feed-forward s1 handoff
// (L1 -> L2, 3 shfl_up width 2), consumed one step later -> off-cycle.
// Unified instruction stream (convergent warp):
//   z_g = CB0*R0eff + CB1*R1 + CB2*R2 + CC0*O0 + CC1*O1 + CC2*O2 + bias
//   L1: CB0 = W1 (R0eff = x dup), CB1 = CB2 = 0, CC = U1 (own h1)
//   L2: CB = W2 (R = received s1),            CC = U2 (own h2)
// 12 gates as 6 f32x2 pairs -> 36 ffma2; cascade = R9 math (7 MUFU/unit,
// 21/step). 8192 lanes = 256 warps in 128 x 64-thread blocks (~1/SMSP).

typedef unsigned long long u64;

#define FULLM 0xFFFFFFFFu
#define LOG2E 1.4426950408889634f

__device__ __forceinline__ float fast_rcp(float x) {
    float r; asm("rcp.approx.f32 %0, %1;" : "=f"(r) : "f"(x)); return r;
}
__device__ __forceinline__ float fast_ex2(float x) {
    float r; asm("ex2.approx.f32 %0, %1;" : "=f"(r) : "f"(x)); return r;
}
__device__ __forceinline__ u64 ffma2(u64 a, u64 b, u64 c) {
    u64 d; asm("fma.rn.f32x2 %0, %1, %2, %3;" : "=l"(d) : "l"(a), "l"(b), "l"(c));
    return d;
}
__device__ __forceinline__ u64 pack2(float lo, float hi) {
    u64 d; asm("mov.b64 %0, {%1, %2};" : "=l"(d) : "f"(lo), "f"(hi)); return d;
}
__device__ __forceinline__ void unpack2(u64 v, float& lo, float& hi) {
    asm("mov.b64 {%0, %1}, %2;" : "=f"(lo), "=f"(hi) : "l"(v));
}

__global__ void __launch_bounds__(64, 1) lstm2_r12_kernel(
    const float* __restrict__ state,
    const float* __restrict__ W1, const float* __restrict__ U1, const float* __restrict__ b1,
    const float* __restrict__ W2, const float* __restrict__ U2, const float* __restrict__ b2,
    const float* __restrict__ Wd, const float* __restrict__ bd,
    float* __restrict__ out, int B, int T)
{
    const int tid  = blockIdx.x * 64 + threadIdx.x;
    const bool isL2 = (tid & 1) != 0;
    int e = tid >> 1;                      // element of this lane pair
    const bool act = (e < B);
    if (!act) e = B - 1;

    // ---- coefficients: j = u*2 + pr, pair pr=0 -> gates (i,f), pr=1 -> (g,o)
    // column(gate) = gate*3 + u; sigma scale -log2e, tanh gate -2log2e.
    u64 CB0[6], CB1[6], CB2[6], CC0[6], CC1[6], CC2[6], BI[6];
#pragma unroll
    for (int u = 0; u < 3; ++u) {
#pragma unroll
        for (int pr = 0; pr < 2; ++pr) {
            const int j   = u * 2 + pr;
            const int glo = pr ? 2 : 0, ghi = pr ? 3 : 1;
            const int clo = glo * 3 + u, chi = ghi * 3 + u;
            const float slo = pr ? (-2.0f * LOG2E) : (-LOG2E);
            const float shi = -LOG2E;
            if (isL2) {
                BI[j]  = pack2(__ldg(b2 + clo) * slo, __ldg(b2 + chi) * shi);
                CB0[j] = pack2(__ldg(W2 + 0 * 12 + clo) * slo, __ldg(W2 + 0 * 12 + chi) * shi);
                CB1[j] = pack2(__ldg(W2 + 1 * 12 + clo) * slo, __ldg(W2 + 1 * 12 + chi) * shi);
                CB2[j] = pack2(__ldg(W2 + 2 * 12 + clo) * slo, __ldg(W2 + 2 * 12 + chi) * shi);
                CC0[j] = pack2(__ldg(U2 + 0 * 12 + clo) * slo, __ldg(U2 + 0 * 12 + chi) * shi);
                CC1[j] = pack2(__ldg(U2 + 1 * 12 + clo) * slo, __ldg(U2 + 1 * 12 + chi) * shi);
                CC2[j] = pack2(__ldg(U2 + 2 * 12 + clo) * slo, __ldg(U2 + 2 * 12 + chi) * shi);
            } else {
                BI[j]  = pack2(__ldg(b1 + clo) * slo, __ldg(b1 + chi) * shi);
                CB0[j] = pack2(__ldg(W1 + clo) * slo, __ldg(W1 + chi) * shi);  // * x
                CB1[j] = 0; CB2[j] = 0;
                CC0[j] = pack2(__ldg(U1 + 0 * 12 + clo) * slo, __ldg(U1 + 0 * 12 + chi) * shi);
                CC1[j] = pack2(__ldg(U1 + 1 * 12 + clo) * slo, __ldg(U1 + 1 * 12 + chi) * shi);
                CC2[j] = pack2(__ldg(U1 + 2 * 12 + clo) * slo, __ldg(U1 + 2 * 12 + chi) * shi);
            }
        }
    }

    const float* xrow = state + (size_t)e * (size_t)T;

    // state: own-layer hidden (O*, dup u64), received s1 (R*, dup u64),
    // own cells (scaled domain), own outputs (scalars).
    u64 O0 = 0, O1 = 0, O2 = 0, R0 = 0, R1 = 0, R2 = 0;
    float cc0 = 0.f, cc1 = 0.f, cc2 = 0.f;
    float ov0 = 0.f, ov1 = 0.f, ov2 = 0.f;

    // cascade for one unit (R9-validated math, 7 MUFU)
#define UNIT(ZA, ZB, CCV, OVV)                                              \
    do {                                                                    \
        float zi, zf, zg, zo;                                               \
        unpack2((ZA), zi, zf); unpack2((ZB), zg, zo);                       \
        const float ei = fast_ex2(zi);                                      \
        const float ef = fast_ex2(zf);                                      \
        const float eg = fast_ex2(zg);                                      \
        const float eo = fast_ex2(zo);                                      \
        const float di = 1.0f + ei, df = 1.0f + ef;                         \
        const float dg = 1.0f + eg, dq = 1.0f + eo;                         \
        const float m1 = di * dg;                                           \
        const float Rm = fast_rcp(m1 * df);                                 \
        const float sf  = Rm * m1;   /* 1/df */                             \
        const float r02 = Rm * df;   /* 1/(di*dg) */                        \
        const float pp  = fmaf(2.0f * LOG2E, eg, -2.0f * LOG2E);            \
        (CCV) = fmaf(sf, (CCV), pp * r02);                                  \
        const float ec = fast_ex2((CCV));                                   \
        const float dc = 1.0f + ec;                                         \
        const float Rq = fast_rcp(dc * dq);                                 \
        (OVV) = (1.0f - ec) * Rq;    /* tanh(c) * sigmoid(o) */             \
    } while (0)

#define STEP(xv)                                                            \
    do {                                                                    \
        const u64 R0e = isL2 ? R0 : pack2((xv), (xv));                      \
        u64 z[6];                                                           \
        _Pragma("unroll")                                                   \
        for (int j = 0; j < 6; ++j) {                                       \
            u64 zz = ffma2(CB0[j], R0e, BI[j]);                             \
            zz = ffma2(CB1[j], R1, zz);                                     \
            zz = ffma2(CB2[j], R2, zz);                                     \
            zz = ffma2(CC0[j], O0, zz);                                     \
            zz = ffma2(CC1[j], O1, zz);                                     \
            zz = ffma2(CC2[j], O2, zz);                                     \
            z[j] = zz;                                                      \
        }                                                                   \
        UNIT(z[0], z[1], cc0, ov0);                                         \
        UNIT(z[2], z[3], cc1, ov1);                                         \
        UNIT(z[4], z[5], cc2, ov2);                                         \
    } while (0)

    // handoff + own-state update (off the recurrence cycle for L2 consume)
#define XFER()                                                              \
    do {                                                                    \
        const float r0 = __shfl_up_sync(FULLM, ov0, 1, 2);                  \
        const float r1 = __shfl_up_sync(FULLM, ov1, 1, 2);                  \
        const float r2 = __shfl_up_sync(FULLM, ov2, 1, 2);                  \
        O0 = pack2(ov0, ov0); O1 = pack2(ov1, ov1); O2 = pack2(ov2, ov2);   \
        R0 = pack2(r0, r0);   R1 = pack2(r1, r1);   R2 = pack2(r2, r2);     \
    } while (0)

#define BODY(xv) do { STEP(xv); XFER(); } while (0)

    // ---- prologue: iter 0. L1 produces s1(0); L2 output is invalid (no
    // h2(-1) / s1(-1)) -> reset L2 state before the handoff.
    float4 a4 = __ldg(reinterpret_cast<const float4*>(xrow));
    float4 nA = a4;
    if (T >= 8) nA = __ldg(reinterpret_cast<const float4*>(xrow + 4));

    STEP(a4.x);
    if (isL2) { cc0 = cc1 = cc2 = 0.f; ov0 = ov1 = ov2 = 0.f; }
    XFER();
    BODY(a4.y);
    BODY(a4.z);
    BODY(a4.w);

    int t = 4;
    for (; t + 7 < T; t += 4) {
        a4 = nA;
        nA = __ldg(reinterpret_cast<const float4*>(xrow + t + 4));
        BODY(a4.x);
        BODY(a4.y);
        BODY(a4.z);
        BODY(a4.w);
    }
    if (t + 3 < T) {                      // last full chunk (already prefetched)
        a4 = nA;
        BODY(a4.x);
        BODY(a4.y);
        BODY(a4.z);
        BODY(a4.w);
        t += 4;
    }
    for (; t < T; ++t) {                  // scalar tail (not taken for T=2048)
        BODY(__ldg(xrow + t));
    }

    // ---- epilogue: one more iter so L2 lanes produce h2(T-1) from s1(T-1).
    // L1 lanes compute garbage (x = 0), never consumed.
    STEP(0.0f);

    if (isL2 && act) {
        float r = __ldg(bd);
        r = fmaf(ov0, __ldg(Wd + 0), r);
        r = fmaf(ov1, __ldg(Wd + 1), r);
        r = fmaf(ov2, __ldg(Wd + 2), r);
        out[e] = r;
    }

#undef UNIT
#undef STEP
#undef XFER
#undef BODY
}

extern "C" void kernel_launch(void* const* d_in, const int* in_sizes, int n_in,
                              void* d_out, int out_size)
{
    const float* state = (const float*)d_in[0];
    const float* W1 = (const float*)d_in[1];
    const float* U1 = (const float*)d_in[2];
    const float* b1 = (const float*)d_in[3];
    const float* W2 = (const float*)d_in[4];
    const float* U2 = (const float*)d_in[5];
    const float* b2 = (const float*)d_in[6];
    const float* Wd = (const float*)d_in[7];
    const float* bd = (const float*)d_in[8];
    float* out = (float*)d_out;

    const int B = out_size;            // output is [1, B]
    const int T = in_sizes[0] / B;     // state is [B, T]

    const int elems_per_block = 32;    // 64 threads = 32 lane pairs
    const int blocks = (B + elems_per_block - 1) / elems_per_block;  // 128
    lstm2_r12_kernel<<<blocks, 64>>>(state, W1, U1, b1, W2, U2, b2,
                                     Wd, bd, out, B, T);
}

// round 13
// speedup vs baseline: 1.1823x; 1.1700x over previous
#include <cuda_runtime.h>

// LSTMBrain: 2-layer LSTM (hidden=3) over [B=4096, T=2048], dense head 3->1.
// Round 13: R9 (best: 313us) with chain surgery only.
//   - 8 lanes/element (0-2: L1 units, 4-6: L2 units, 3/7 dup), 4 elems/warp,
//     1024 warps (~1.73/SMSP), smem exchange (STS.64 dup + syncwarp + 3 LDS.128).
//   - z matvec as TWO 3-deep ffma2 trees + fadd2 (12 cyc from S-arrival).
//   - MUFU issue order: (g,o) z-half first -> eg,eo issued while the (i,f)
//     half's FMAs fill the ex2 rt-8 gaps; pp/dq ready before Rm.
//   - cascade unchanged (7 MUFU: 4 gate ex2 + cell ex2 + 2 rcp) -> rel_err same.

typedef unsigned long long u64;

#define FULLM 0xFFFFFFFFu
#define LOG2E 1.4426950408889634f

__device__ __forceinline__ float fast_rcp(float x) {
    float r; asm("rcp.approx.f32 %0, %1;" : "=f"(r) : "f"(x)); return r;
}
__device__ __forceinline__ float fast_ex2(float x) {
    float r; asm("ex2.approx.f32 %0, %1;" : "=f"(r) : "f"(x)); return r;
}
__device__ __forceinline__ u64 ffma2(u64 a, u64 b, u64 c) {
    u64 d; asm("fma.rn.f32x2 %0, %1, %2, %3;" : "=l"(d) : "l"(a), "l"(b), "l"(c));
    return d;
}
__device__ __forceinline__ u64 fmul2(u64 a, u64 b) {
    u64 d; asm("mul.rn.f32x2 %0, %1, %2;" : "=l"(d) : "l"(a), "l"(b)); return d;
}
__device__ __forceinline__ u64 fadd2(u64 a, u64 b) {
    u64 d; asm("add.rn.f32x2 %0, %1, %2;" : "=l"(d) : "l"(a), "l"(b)); return d;
}
__device__ __forceinline__ u64 pack2(float lo, float hi) {
    u64 d; asm("mov.b64 %0, {%1, %2};" : "=l"(d) : "f"(lo), "f"(hi)); return d;
}
__device__ __forceinline__ void unpack2(u64 v, float& lo, float& hi) {
    asm("mov.b64 {%0, %1}, %2;" : "=f"(lo), "=f"(hi) : "l"(v));
}

__global__ void __launch_bounds__(32, 1) lstm2_r13_kernel(
    const float* __restrict__ state,
    const float* __restrict__ W1, const float* __restrict__ U1, const float* __restrict__ b1,
    const float* __restrict__ W2, const float* __restrict__ U2, const float* __restrict__ b2,
    const float* __restrict__ Wd, const float* __restrict__ bd,
    float* __restrict__ out, int B, int T)
{
    __shared__ __align__(16) u64 xch[2][32];   // [buffer][slot], (v,v) dup

    const int lane  = threadIdx.x & 31;
    const int lane8 = lane & 7;
    const int gbase = lane & ~7;               // group's first lane/slot
    const int sub   = lane8 & 3;
    const int u     = (sub < 3) ? sub : 2;     // owned hidden unit (3/7 dup 2)
    const bool isL2 = (lane8 & 4) != 0;
    // permuted write slot: roles 0,1,2 -> 0,1,2 ; 4,5,6 -> 3,4,5 ; 3->6, 7->7
    const int sslot = gbase + ((lane8 < 3) ? lane8
                        : (lane8 == 3) ? 6
                        : (lane8 < 7) ? (lane8 - 1) : 7);

    int e = blockIdx.x * 4 + (lane >> 3);      // element of this group
    const bool act = (e < B);
    if (!act) e = B - 1;

    // ---- gate-pair packed coefficients, pre-scaled into the ex2 domain ----
    // pair 0 = gates (g, o)  [computed FIRST for MUFU issue order]
    // pair 1 = gates (i, f); column(gate) = gate*3 + u
    u64 AP[2], BIP[2], BP[3][2], CP[3][2];
#pragma unroll
    for (int pr = 0; pr < 2; ++pr) {
        const int glo = (pr == 0) ? 2 : 0;     // g or i
        const int ghi = (pr == 0) ? 3 : 1;     // o or f
        const int clo = glo * 3 + u, chi = ghi * 3 + u;
        const float slo = (glo == 2) ? (-2.0f * LOG2E) : (-LOG2E);
        const float shi = -LOG2E;
        if (isL2) {
            AP[pr]  = 0;
            BIP[pr] = pack2(__ldg(b2 + clo) * slo, __ldg(b2 + chi) * shi);
#pragma unroll
            for (int k = 0; k < 3; ++k) {
                BP[k][pr] = pack2(__ldg(W2 + k * 12 + clo) * slo,
                                  __ldg(W2 + k * 12 + chi) * shi);  // * s1
                CP[k][pr] = pack2(__ldg(U2 + k * 12 + clo) * slo,
                                  __ldg(U2 + k * 12 + chi) * shi);  // * h2
            }
        } else {
            AP[pr]  = pack2(__ldg(W1 + clo) * slo, __ldg(W1 + chi) * shi);
            BIP[pr] = pack2(__ldg(b1 + clo) * slo, __ldg(b1 + chi) * shi);
#pragma unroll
            for (int k = 0; k < 3; ++k) {
                BP[k][pr] = pack2(__ldg(U1 + k * 12 + clo) * slo,
                                  __ldg(U1 + k * 12 + chi) * shi);  // * s1
                CP[k][pr] = 0;
            }
        }
    }

    const float* xrow = state + (size_t)e * (size_t)T;

    float cc   = 0.f;                     // own-unit scaled cell state
    float outv = 0.f;                     // own-unit hidden output
    u64 S0 = 0, S1 = 0, S2 = 0;           // duplicated s1(t-1) broadcasts
    u64 H0 = 0, H1 = 0, H2 = 0;           // duplicated h2(t-2) broadcasts

    // STEP: (g,o) z tree first -> eg,eo issued early; (i,f) z tree fills the
    // ex2 rt gaps; cascade: 7 MUFU total, rcp tricks as in R9.
#define STEP(xv)                                                            \
    do {                                                                    \
        const u64 xp = pack2((xv), (xv));                                   \
        /* pair 0: gates (g,o) -- two 3-deep halves + add */                \
        u64 g1 = ffma2(BP[1][0], S1,                                        \
                   ffma2(BP[0][0], S0, ffma2(AP[0], xp, BIP[0])));          \
        u64 g2 = ffma2(CP[2][0], H2,                                        \
                   ffma2(CP[1][0], H1,                                      \
                     ffma2(CP[0][0], H0, fmul2(BP[2][0], S2))));            \
        const u64 zgo = fadd2(g1, g2);                                      \
        float zg, zo;                                                       \
        unpack2(zgo, zg, zo);                                               \
        const float eg = fast_ex2(zg);                                      \
        const float eo = fast_ex2(zo);                                      \
        /* pair 1: gates (i,f) -- issued while eg/eo are in flight */       \
        u64 i1 = ffma2(BP[1][1], S1,                                        \
                   ffma2(BP[0][1], S0, ffma2(AP[1], xp, BIP[1])));          \
        u64 i2 = ffma2(CP[2][1], H2,                                        \
                   ffma2(CP[1][1], H1,                                      \
                     ffma2(CP[0][1], H0, fmul2(BP[2][1], S2))));            \
        const u64 zif = fadd2(i1, i2);                                      \
        float zi, zf;                                                       \
        unpack2(zif, zi, zf);                                               \
        const float ei = fast_ex2(zi);                                      \
        const float ef = fast_ex2(zf);                                      \
        /* early consumers of eg/eo (ready before Rm) */                    \
        const float pp = fmaf(2.0f * LOG2E, eg, -2.0f * LOG2E);             \
        const float dg = 1.0f + eg;                                         \
        const float dq = 1.0f + eo;                                         \
        const float di = 1.0f + ei;                                         \
        const float df = 1.0f + ef;                                         \
        const float m1 = di * dg;                                           \
        const float Rm = fast_rcp(m1 * df);                                 \
        const float sf  = Rm * m1;    /* 1/df */                            \
        const float r02 = Rm * df;    /* 1/(di*dg) */                       \
        cc = fmaf(sf, cc, pp * r02);                                        \
        const float ec = fast_ex2(cc);                                      \
        const float dc = 1.0f + ec;                                         \
        const float Rq = fast_rcp(dc * dq);                                 \
        outv = (1.0f - ec) * Rq;      /* tanh(c) * sigmoid(o) */            \
    } while (0)

    // exchange: duplicated STS.64 into permuted slot, syncwarp, 3x LDS.128
#define XCHG(p)                                                             \
    do {                                                                    \
        xch[(p)][sslot] = pack2(outv, outv);                                \
        __syncwarp(FULLM);                                                  \
        const ulonglong2 v0 =                                               \
            *reinterpret_cast<const ulonglong2*>(&xch[(p)][gbase]);         \
        const ulonglong2 v1 =                                               \
            *reinterpret_cast<const ulonglong2*>(&xch[(p)][gbase + 2]);     \
        const ulonglong2 v2 =                                               \
            *reinterpret_cast<const ulonglong2*>(&xch[(p)][gbase + 4]);     \
        S0 = v0.x; S1 = v0.y; S2 = v1.x;                                    \
        H0 = v1.y; H1 = v2.x; H2 = v2.y;                                    \
    } while (0)

#define BODY(xv, p) do { STEP(xv); XCHG(p); } while (0)

    // ---- prologue: t = 0 (L2 lanes reset: no h2(-1)/s1(-1)), then t = 1..3
    float4 a4 = __ldg(reinterpret_cast<const float4*>(xrow));
    float4 nA = a4;
    if (T >= 8) nA = __ldg(reinterpret_cast<const float4*>(xrow + 4));

    STEP(a4.x);
    if (isL2) { cc = 0.f; outv = 0.f; }
    XCHG(0);
    BODY(a4.y, 1);
    BODY(a4.z, 0);
    BODY(a4.w, 1);

    int t = 4;
    for (; t + 7 < T; t += 4) {
        a4 = nA;
        nA = __ldg(reinterpret_cast<const float4*>(xrow + t + 4));
        BODY(a4.x, 0);
        BODY(a4.y, 1);
        BODY(a4.z, 0);
        BODY(a4.w, 1);
    }
    if (t + 3 < T) {                      // last full chunk (already prefetched)
        a4 = nA;
        BODY(a4.x, 0);
        BODY(a4.y, 1);
        BODY(a4.z, 0);
        BODY(a4.w, 1);
        t += 4;
    }
    for (; t < T; ++t) {                  // scalar tail (not taken for T=2048)
        BODY(__ldg(xrow + t), t & 1);
    }

    // ---- epilogue: one more step so L2 lanes produce h2(T-1). x unused by
    // L2 (A = 0); L1 lanes' output is never consumed.
    STEP(0.0f);
    xch[0][sslot] = pack2(outv, outv);
    __syncwarp(FULLM);

    if (lane8 == 0 && act) {
        float f0, f1, f2, junk;
        unpack2(xch[0][gbase + 3], f0, junk);   // h2 unit 0 (permuted slots)
        unpack2(xch[0][gbase + 4], f1, junk);   // h2 unit 1
        unpack2(xch[0][gbase + 5], f2, junk);   // h2 unit 2
        float r = __ldg(bd);
        r = fmaf(f0, __ldg(Wd + 0), r);
        r = fmaf(f1, __ldg(Wd + 1), r);
        r = fmaf(f2, __ldg(Wd + 2), r);
        out[e] = r;
    }

#undef STEP
#undef XCHG
#undef BODY
}

extern "C" void kernel_launch(void* const* d_in, const int* in_sizes, int n_in,
                              void* d_out, int out_size)
{
    const float* state = (const float*)d_in[0];
    const float* W1 = (const float*)d_in[1];
    const float* U1 = (const float*)d_in[2];
    const float* b1 = (const float*)d_in[3];
    const float* W2 = (const float*)d_in[4];
    const float* U2 = (const float*)d_in[5];
    const float* b2 = (const float*)d_in[6];
    const float* Wd = (const float*)d_in[7];
    const float* bd = (const float*)d_in[8];
    float* out = (float*)d_out;

    const int B = out_size;            // output is [1, B]
    const int T = in_sizes[0] / B;     // state is [B, T]

    const int elems_per_warp = 4;      // 4 groups x 8 lanes = 32
    const int blocks = (B + elems_per_warp - 1) / elems_per_warp;   // 1024
    lstm2_r13_kernel<<<blocks, 32>>>(state, W1, U1, b1, W2, U2, b2,
                                     Wd, bd, out, B, T);
}

// round 14
// speedup vs baseline: 1.2929x; 1.0935x over previous
#include <cuda_runtime.h>

// LSTMBrain: 2-layer LSTM (hidden=3) over [B=4096, T=2048], dense head 3->1.
// Round 14: R9 (best, 313us) with ONE change: duplicate lanes removed.
//   6-lane groups: role 0-2 = L1 unit, role 3-5 = L2 unit. 5 elements/warp
//   (lanes 30-31 idle on a clamped element, kept convergent). 820 warps
//   (was 1024) -> 1.39 warps/SMSP -> less cross-warp MUFU-queue interference
//   on the chain-critical ex2/rcp ops.
// STEP / cascade / exchange are copied from R9 verbatim (serial z, (i,f)
// pair first, 7 MUFU: 4 gate ex2 + cell ex2 + rcp(m1*df) + rcp(dc*dq)).
// Exchange slots at stride 8 per group keep the 3x LDS.128 reads aligned.

typedef unsigned long long u64;

#define FULLM 0xFFFFFFFFu
#define LOG2E 1.4426950408889634f

__device__ __forceinline__ float fast_rcp(float x) {
    float r; asm("rcp.approx.f32 %0, %1;" : "=f"(r) : "f"(x)); return r;
}
__device__ __forceinline__ float fast_ex2(float x) {
    float r; asm("ex2.approx.f32 %0, %1;" : "=f"(r) : "f"(x)); return r;
}
__device__ __forceinline__ u64 ffma2(u64 a, u64 b, u64 c) {
    u64 d; asm("fma.rn.f32x2 %0, %1, %2, %3;" : "=l"(d) : "l"(a), "l"(b), "l"(c));
    return d;
}
__device__ __forceinline__ u64 pack2(float lo, float hi) {
    u64 d; asm("mov.b64 %0, {%1, %2};" : "=l"(d) : "f"(lo), "f"(hi)); return d;
}
__device__ __forceinline__ void unpack2(u64 v, float& lo, float& hi) {
    asm("mov.b64 {%0, %1}, %2;" : "=f"(lo), "=f"(hi) : "l"(v));
}

__global__ void __launch_bounds__(32, 1) lstm2_r14_kernel(
    const float* __restrict__ state,
    const float* __restrict__ W1, const float* __restrict__ U1, const float* __restrict__ b1,
    const float* __restrict__ W2, const float* __restrict__ U2, const float* __restrict__ b2,
    const float* __restrict__ Wd, const float* __restrict__ bd,
    float* __restrict__ out, int B, int T)
{
    __shared__ __align__(16) u64 xch[2][48];   // [buffer][slot], (v,v) dup; stride 8/group

    const int lane  = threadIdx.x & 31;
    const int group = lane / 6;                // 0..4 real, 5 = idle lanes 30-31
    const int role  = lane - group * 6;        // 0..5 (idle lanes: 0..1)
    const int base  = group * 8;               // slot base (64B aligned)
    const bool isL2 = (role >= 3);
    const int u     = isL2 ? (role - 3) : role;  // owned hidden unit
    const int sslot = base + role;             // write slot (idle -> 40/41, harmless)

    int e = blockIdx.x * 5 + group;            // element of this group
    const bool act = (e < B) && (group < 5);
    if (e >= B) e = B - 1;

    // ---- gate-pair packed coefficients, pre-scaled into the ex2 domain ----
    // pair 0 = gates (i, f)  [f-path is chain-critical: computed FIRST]
    // pair 1 = gates (g, o); column(gate) = gate*3 + u
    u64 AP[2], BIP[2], BP[3][2], CP[3][2];
#pragma unroll
    for (int pr = 0; pr < 2; ++pr) {
        const int glo = (pr == 0) ? 0 : 2;     // i or g
        const int ghi = (pr == 0) ? 1 : 3;     // f or o
        const int clo = glo * 3 + u, chi = ghi * 3 + u;
        const float slo = (glo == 2) ? (-2.0f * LOG2E) : (-LOG2E);
        const float shi = -LOG2E;
        if (isL2) {
            AP[pr]  = 0;
            BIP[pr] = pack2(__ldg(b2 + clo) * slo, __ldg(b2 + chi) * shi);
#pragma unroll
            for (int k = 0; k < 3; ++k) {
                BP[k][pr] = pack2(__ldg(W2 + k * 12 + clo) * slo,
                                  __ldg(W2 + k * 12 + chi) * shi);  // * s1
                CP[k][pr] = pack2(__ldg(U2 + k * 12 + clo) * slo,
                                  __ldg(U2 + k * 12 + chi) * shi);  // * h2
            }
        } else {
            AP[pr]  = pack2(__ldg(W1 + clo) * slo, __ldg(W1 + chi) * shi);
            BIP[pr] = pack2(__ldg(b1 + clo) * slo, __ldg(b1 + chi) * shi);
#pragma unroll
            for (int k = 0; k < 3; ++k) {
                BP[k][pr] = pack2(__ldg(U1 + k * 12 + clo) * slo,
                                  __ldg(U1 + k * 12 + chi) * shi);  // * s1
                CP[k][pr] = 0;
            }
        }
    }

    const float* xrow = state + (size_t)e * (size_t)T;

    float cc   = 0.f;                     // own-unit scaled cell state
    float outv = 0.f;                     // own-unit hidden output
    u64 S0 = 0, S1 = 0, S2 = 0;           // duplicated s1(t-1) broadcasts
    u64 H0 = 0, H1 = 0, H2 = 0;           // duplicated h2(t-2) broadcasts

    // STEP: verbatim R9 (serial z per pair, (i,f) first; 7-MUFU cascade)
#define STEP(xv)                                                            \
    do {                                                                    \
        const u64 xp = pack2((xv), (xv));                                   \
        u64 za = ffma2(AP[0], xp, BIP[0]);                                  \
        u64 zb = ffma2(AP[1], xp, BIP[1]);                                  \
        za = ffma2(BP[0][0], S0, za); zb = ffma2(BP[0][1], S0, zb);         \
        za = ffma2(BP[1][0], S1, za); zb = ffma2(BP[1][1], S1, zb);         \
        za = ffma2(BP[2][0], S2, za); zb = ffma2(BP[2][1], S2, zb);         \
        za = ffma2(CP[0][0], H0, za); zb = ffma2(CP[0][1], H0, zb);         \
        za = ffma2(CP[1][0], H1, za); zb = ffma2(CP[1][1], H1, zb);         \
        za = ffma2(CP[2][0], H2, za); zb = ffma2(CP[2][1], H2, zb);         \
        float zi, zf, zg, zo;                                               \
        unpack2(za, zi, zf); unpack2(zb, zg, zo);                           \
        const float ei = fast_ex2(zi);                                      \
        const float ef = fast_ex2(zf);                                      \
        const float eg = fast_ex2(zg);                                      \
        const float eo = fast_ex2(zo);                                      \
        const float di = 1.0f + ei, df = 1.0f + ef;                         \
        const float dg = 1.0f + eg, dq = 1.0f + eo;                         \
        const float m1 = di * dg;                                           \
        const float Rm = fast_rcp(m1 * df);                                 \
        const float sf  = Rm * m1;    /* 1/df */                            \
        const float r02 = Rm * df;    /* 1/(di*dg) */                       \
        const float pp  = fmaf(2.0f * LOG2E, eg, -2.0f * LOG2E);            \
        cc = fmaf(sf, cc, pp * r02);                                        \
        const float ec = fast_ex2(cc);                                      \
        const float dc = 1.0f + ec;                                         \
        const float Rq = fast_rcp(dc * dq);                                 \
        outv = (1.0f - ec) * Rq;      /* tanh(c) * sigmoid(o) */            \
    } while (0)

    // exchange: duplicated STS.64, one syncwarp, 3x LDS.128 (aligned: base*8B)
#define XCHG(p)                                                             \
    do {                                                                    \
        xch[(p)][sslot] = pack2(outv, outv);                                \
        __syncwarp(FULLM);                                                  \
        const ulonglong2 v0 =                                               \
            *reinterpret_cast<const ulonglong2*>(&xch[(p)][base]);          \
        const ulonglong2 v1 =                                               \
            *reinterpret_cast<const ulonglong2*>(&xch[(p)][base + 2]);      \
        const ulonglong2 v2 =                                               \
            *reinterpret_cast<const ulonglong2*>(&xch[(p)][base + 4]);      \
        S0 = v0.x; S1 = v0.y; S2 = v1.x;                                    \
        H0 = v1.y; H1 = v2.x; H2 = v2.y;                                    \
    } while (0)

#define BODY(xv, p) do { STEP(xv); XCHG(p); } while (0)

    // ---- prologue: t = 0 (L2 lanes reset: no h2(-1)/s1(-1)), then t = 1..3
    float4 a4 = __ldg(reinterpret_cast<const float4*>(xrow));
    float4 nA = a4;
    if (T >= 8) nA = __ldg(reinterpret_cast<const float4*>(xrow + 4));

    STEP(a4.x);
    if (isL2) { cc = 0.f; outv = 0.f; }
    XCHG(0);
    BODY(a4.y, 1);
    BODY(a4.z, 0);
    BODY(a4.w, 1);

    int t = 4;
    for (; t + 7 < T; t += 4) {
        a4 = nA;
        nA = __ldg(reinterpret_cast<const float4*>(xrow + t + 4));
        BODY(a4.x, 0);
        BODY(a4.y, 1);
        BODY(a4.z, 0);
        BODY(a4.w, 1);
    }
    if (t + 3 < T) {                      // last full chunk (already prefetched)
        a4 = nA;
        BODY(a4.x, 0);
        BODY(a4.y, 1);
        BODY(a4.z, 0);
        BODY(a4.w, 1);
        t += 4;
    }
    for (; t < T; ++t) {                  // scalar tail (not taken for T=2048)
        BODY(__ldg(xrow + t), t & 1);
    }

    // ---- epilogue: one more step so L2 lanes produce h2(T-1). x unused by
    // L2 (A = 0); L1 lanes' output is never consumed.
    STEP(0.0f);
    xch[0][sslot] = pack2(outv, outv);
    __syncwarp(FULLM);

    if (role == 0 && act) {
        float f0, f1, f2, junk;
        unpack2(xch[0][base + 3], f0, junk);   // h2 unit 0
        unpack2(xch[0][base + 4], f1, junk);   // h2 unit 1
        unpack2(xch[0][base + 5], f2, junk);   // h2 unit 2
        float r = __ldg(bd);
        r = fmaf(f0, __ldg(Wd + 0), r);
        r = fmaf(f1, __ldg(Wd + 1), r);
        r = fmaf(f2, __ldg(Wd + 2), r);
        out[e] = r;
    }

#undef STEP
#undef XCHG
#undef BODY
}

extern "C" void kernel_launch(void* const* d_in, const int* in_sizes, int n_in,
                              void* d_out, int out_size)
{
    const float* state = (const float*)d_in[0];
    const float* W1 = (const float*)d_in[1];
    const float* U1 = (const float*)d_in[2];
    const float* b1 = (const float*)d_in[3];
    const float* W2 = (const float*)d_in[4];
    const float* U2 = (const float*)d_in[5];
    const float* b2 = (const float*)d_in[6];
    const float* Wd = (const float*)d_in[7];
    const float* bd = (const float*)d_in[8];
    float* out = (float*)d_out;

    const int B = out_size;            // output is [1, B]
    const int T = in_sizes[0] / B;     // state is [B, T]

    const int elems_per_warp = 5;      // 5 groups x 6 lanes (+2 idle)
    const int blocks = (B + elems_per_warp - 1) / elems_per_warp;   // 820
    lstm2_r14_kernel<<<blocks, 32>>>(state, W1, U1, b1, W2, U2, b2,
                                     Wd, bd, out, B, T);
}